// round 9
// baseline (speedup 1.0000x reference)
#include <cuda_runtime.h>
#include <cuda_bf16.h>
#include <math.h>
#include <stdint.h>

// LogMap via matrix polynomial on the tensor pipe (portable mma.sync m16n8k16 bf16).
// log(X) = p(S), S=(X-m I)/h on [1,6.8]; p = deg-8 Chebyshev fit of log.
// Sastre-style evaluation: 3 matrix products (was 4):
//   Z = S^2;  W = Z*(Z + c1 S);  p(S) = (p8 W + c3 Z + c4 S + c5 I)*(W + c7 S)
//             + c10 Z + c11 S + c12 I
// Each fp32 product = 3 bf16 MMAs (hi/lo split). 1 matrix/CTA, 4 warps,
// launch_bounds(128,4) -> 4 CTAs/SM. W never round-trips SMEM (acc->A frags);
// r is stored fused (gamma*W + gamma*c7*S) into the V buffer.

#define DEG 8
struct Coeffs {
    float mshift, invh;
    float c1;                   // V = Z + c1 S
    float qa, qb, qc, qd;       // q = qa*W + qb*Z + qc*S + qd*I   (already /gamma)
    float ra, rb;               // r = ra*W + rb*S                 (already *gamma)
    float f0, f1, f2;           // final += f0*I + f1*S + f2*Z
};

// smem byte offsets: 6 buffers of 64 rows x 128 B
#define SH 0
#define SL 8192
#define ZH 16384
#define ZL 24576
#define VH 32768
#define VL 40960
#define SMEM_TOTAL 49152

__device__ __forceinline__ uint32_t smem_u32(const void* p) {
    uint32_t a;
    asm("{ .reg .u64 t; cvta.to.shared.u64 t, %1; cvt.u32.u64 %0, t; }"
        : "=r"(a) : "l"(p));
    return a;
}

__device__ __forceinline__ uint32_t swoff(int r, int cb) {
    return (uint32_t)(r * 128 + ((((cb >> 4) ^ (r & 7))) << 4) + (cb & 15));
}

#define LDMX4(d, addr) \
    asm volatile("ldmatrix.sync.aligned.m8n8.x4.shared.b16 {%0,%1,%2,%3}, [%4];" \
        : "=r"((d)[0]), "=r"((d)[1]), "=r"((d)[2]), "=r"((d)[3]) : "r"(addr))

#define LDMX4T(d, addr) \
    asm volatile("ldmatrix.sync.aligned.m8n8.x4.trans.shared.b16 {%0,%1,%2,%3}, [%4];" \
        : "=r"((d)[0]), "=r"((d)[1]), "=r"((d)[2]), "=r"((d)[3]) : "r"(addr))

#define MMA(c, a, b0v, b1v) \
    asm volatile("mma.sync.aligned.m16n8k16.row.col.f32.bf16.bf16.f32 " \
        "{%0,%1,%2,%3}, {%4,%5,%6,%7}, {%8,%9}, {%0,%1,%2,%3};" \
        : "+f"((c)[0]), "+f"((c)[1]), "+f"((c)[2]), "+f"((c)[3]) \
        : "r"((a)[0]), "r"((a)[1]), "r"((a)[2]), "r"((a)[3]), "r"(b0v), "r"(b1v))

__device__ __forceinline__ uint32_t pk(float a, float b) {
    __nv_bfloat162 t = __floats2bfloat162_rn(a, b);
    return *reinterpret_cast<uint32_t*>(&t);
}
__device__ __forceinline__ float2 upk(uint32_t u) {
    __nv_bfloat162 t = *reinterpret_cast<__nv_bfloat162*>(&u);
    return __bfloat1622float2(t);
}
__device__ __forceinline__ float bhi(float v) {
    return __bfloat162float(__float2bfloat16_rn(v));
}

__device__ __forceinline__ void split_store8(const float* v, char* hi, char* lo) {
    float h0 = bhi(v[0]), h1 = bhi(v[1]), h2 = bhi(v[2]), h3 = bhi(v[3]);
    float h4 = bhi(v[4]), h5 = bhi(v[5]), h6 = bhi(v[6]), h7 = bhi(v[7]);
    *(uint4*)hi = make_uint4(pk(v[0], v[1]), pk(v[2], v[3]), pk(v[4], v[5]), pk(v[6], v[7]));
    *(uint4*)lo = make_uint4(pk(v[0]-h0, v[1]-h1), pk(v[2]-h2, v[3]-h3),
                             pk(v[4]-h4, v[5]-h5), pk(v[6]-h6, v[7]-h7));
}

__global__ void __launch_bounds__(128, 4)
logmap_mma_kernel(const float* __restrict__ X, float* __restrict__ out, Coeffs cf)
{
    extern __shared__ char sm[];
    const uint32_t sb = smem_u32(sm);
    const int tid = threadIdx.x;
    const int w = tid >> 5;              // warp owns rows [16w, 16w+16)
    const int l = tid & 31;
    const int sr = 16 * w;
    const int lq = l >> 2, lr = l & 3;
    const int lmr = l & 15;
    const int lmc16 = (l >> 4) & 1;
    const int key = lmr & 7;
    const size_t mb = (size_t)blockIdx.x * 4096;

    uint32_t colx[4];
    #pragma unroll
    for (int j = 0; j < 4; j++) colx[j] = (uint32_t)((((2*j + lmc16) ^ key)) << 4);
    const uint32_t arow = (uint32_t)((sr + lmr) * 128);
    const int er0 = sr + lq, er1 = er0 + 8;

    // ---- load X (half-row per thread), S = (X - m I)/h, write S hi/lo ----
    {
        const int row = sr + (l >> 1);
        const int c0 = 32 * (l & 1);
        const float4* xr = (const float4*)(X + mb + (size_t)row * 64 + c0);
        float v[32];
        #pragma unroll
        for (int q = 0; q < 8; q++) {
            float4 f = xr[q];
            v[4*q] = f.x; v[4*q+1] = f.y; v[4*q+2] = f.z; v[4*q+3] = f.w;
        }
        #pragma unroll
        for (int i = 0; i < 32; i++) {
            float t = v[i];
            if (c0 + i == row) t -= cf.mshift;
            v[i] = t * cf.invh;
        }
        #pragma unroll
        for (int q = 0; q < 4; q++) {
            uint32_t o = swoff(row, 2 * c0 + 16 * q);
            split_store8(v + 8 * q, sm + SH + o, sm + SL + o);
        }
    }
    __syncthreads();

    float acc[8][4];
    uint32_t ah[4][4], al[4][4];

    auto zacc = [&] {
        #pragma unroll
        for (int n = 0; n < 8; n++)
            #pragma unroll
            for (int q = 0; q < 4; q++) acc[n][q] = 0.f;
    };

    auto ldaS = [&] {
        #pragma unroll
        for (int kk = 0; kk < 4; kk++) {
            uint32_t o = arow + colx[kk];
            LDMX4(ah[kk], sb + SH + o);
            LDMX4(al[kk], sb + SL + o);
        }
    };

    auto cvtA = [&] {
        #pragma unroll
        for (int kk = 0; kk < 4; kk++) {
            float c00 = acc[2*kk][0],   c01 = acc[2*kk][1];
            float c02 = acc[2*kk][2],   c03 = acc[2*kk][3];
            float d00 = acc[2*kk+1][0], d01 = acc[2*kk+1][1];
            float d02 = acc[2*kk+1][2], d03 = acc[2*kk+1][3];
            ah[kk][0] = pk(c00, c01); ah[kk][1] = pk(c02, c03);
            ah[kk][2] = pk(d00, d01); ah[kk][3] = pk(d02, d03);
            al[kk][0] = pk(c00 - bhi(c00), c01 - bhi(c01));
            al[kk][1] = pk(c02 - bhi(c02), c03 - bhi(c03));
            al[kk][2] = pk(d00 - bhi(d00), d01 - bhi(d01));
            al[kk][3] = pk(d02 - bhi(d02), d03 - bhi(d03));
        }
    };

    auto product = [&](uint32_t bhBase, uint32_t blBase) {
        #pragma unroll
        for (int kk = 0; kk < 4; kk++) {
            const uint32_t kbo = (uint32_t)((16*kk + lmr) * 128);
            #pragma unroll
            for (int jp = 0; jp < 2; jp++) {
                uint32_t o0 = kbo + colx[2*jp], o1 = kbo + colx[2*jp + 1];
                uint32_t b0[4], b1[4];
                LDMX4T(b0, bhBase + o0);
                LDMX4T(b1, bhBase + o1);
                MMA(acc[4*jp+0], ah[kk], b0[0], b0[1]);
                MMA(acc[4*jp+1], ah[kk], b0[2], b0[3]);
                MMA(acc[4*jp+2], ah[kk], b1[0], b1[1]);
                MMA(acc[4*jp+3], ah[kk], b1[2], b1[3]);
                MMA(acc[4*jp+0], al[kk], b0[0], b0[1]);
                MMA(acc[4*jp+1], al[kk], b0[2], b0[3]);
                MMA(acc[4*jp+2], al[kk], b1[0], b1[1]);
                MMA(acc[4*jp+3], al[kk], b1[2], b1[3]);
                LDMX4T(b0, blBase + o0);
                LDMX4T(b1, blBase + o1);
                MMA(acc[4*jp+0], ah[kk], b0[0], b0[1]);
                MMA(acc[4*jp+1], ah[kk], b0[2], b0[3]);
                MMA(acc[4*jp+2], ah[kk], b1[0], b1[1]);
                MMA(acc[4*jp+3], ah[kk], b1[2], b1[3]);
            }
        }
    };

    // store sc*acc + cS*S into buffer pair (hi/lo bf16 split)
    auto stacc_plus = [&](int hB, int lB, float sc, float cS) {
        #pragma unroll
        for (int n = 0; n < 8; n++) {
            int cb = 16 * n + 4 * lr;
            uint32_t o0 = swoff(er0, cb), o1 = swoff(er1, cb);
            float2 s0 = upk(*(uint32_t*)(sm + SH + o0));
            float2 s0l = upk(*(uint32_t*)(sm + SL + o0));
            float2 s1 = upk(*(uint32_t*)(sm + SH + o1));
            float2 s1l = upk(*(uint32_t*)(sm + SL + o1));
            float a0 = sc * acc[n][0] + cS * (s0.x + s0l.x);
            float a1 = sc * acc[n][1] + cS * (s0.y + s0l.y);
            float a2 = sc * acc[n][2] + cS * (s1.x + s1l.x);
            float a3 = sc * acc[n][3] + cS * (s1.y + s1l.y);
            *(uint32_t*)(sm + hB + o0) = pk(a0, a1);
            *(uint32_t*)(sm + hB + o1) = pk(a2, a3);
            *(uint32_t*)(sm + lB + o0) = pk(a0 - bhi(a0), a1 - bhi(a1));
            *(uint32_t*)(sm + lB + o1) = pk(a2 - bhi(a2), a3 - bhi(a3));
        }
    };

    // plain store of acc into buffer pair
    auto stacc = [&](int hB, int lB) {
        #pragma unroll
        for (int n = 0; n < 8; n++) {
            int cb = 16 * n + 4 * lr;
            uint32_t o0 = swoff(er0, cb), o1 = swoff(er1, cb);
            float a0 = acc[n][0], a1 = acc[n][1];
            float a2 = acc[n][2], a3 = acc[n][3];
            *(uint32_t*)(sm + hB + o0) = pk(a0, a1);
            *(uint32_t*)(sm + hB + o1) = pk(a2, a3);
            *(uint32_t*)(sm + lB + o0) = pk(a0 - bhi(a0), a1 - bhi(a1));
            *(uint32_t*)(sm + lB + o1) = pk(a2 - bhi(a2), a3 - bhi(a3));
        }
    };

    // acc = a*acc + b0*I + b1*S + b2*Z
    auto epi_scaled = [&](float a, float b0, float b1, float b2) {
        #pragma unroll
        for (int g = 0; g < 4; g++) {
            uint32_t shf[4], slf[4], zhf[4], zlf[4];
            uint32_t o = arow + colx[g];
            LDMX4(shf, sb + SH + o);
            LDMX4(slf, sb + SL + o);
            LDMX4(zhf, sb + ZH + o);
            LDMX4(zlf, sb + ZL + o);
            #pragma unroll
            for (int q = 0; q < 4; q++) {
                float2 s = upk(shf[q]), s2 = upk(slf[q]);
                float2 z = upk(zhf[q]), z2 = upk(zlf[q]);
                float sx = s.x + s2.x, sy = s.y + s2.y;
                float zx = z.x + z2.x, zy = z.y + z2.y;
                int n = 2 * g + (q >> 1), c = (q & 1) * 2;
                acc[n][c]     = a * acc[n][c]     + b1 * sx + b2 * zx;
                acc[n][c + 1] = a * acc[n][c + 1] + b1 * sy + b2 * zy;
            }
        }
        #pragma unroll
        for (int n = 0; n < 8; n++) {
            int c0 = 8 * n + 2 * lr;
            if (c0 == er0)     acc[n][0] += b0;
            if (c0 + 1 == er0) acc[n][1] += b0;
            if (c0 == er1)     acc[n][2] += b0;
            if (c0 + 1 == er1) acc[n][3] += b0;
        }
    };

    // ---- product 1: Z = S*S ----
    ldaS();
    zacc();
    product(sb + SH, sb + SL);
    cvtA();                              // A <- Z
    stacc(ZH, ZL);                       // Z -> smem
    stacc_plus(VH, VL, 1.0f, cf.c1);     // V = Z + c1 S -> smem
    __syncthreads();

    // ---- product 2: W = Z*V ----
    zacc();
    product(sb + VH, sb + VL);
    __syncthreads();                     // all warps done reading V
    stacc_plus(VH, VL, cf.ra, cf.rb);    // r = ra*W + rb*S -> V buffer
    epi_scaled(cf.qa, cf.qd, cf.qc, cf.qb);  // acc = qa*W + qd*I + qc*S + qb*Z
    cvtA();                              // A <- q
    __syncthreads();                     // r visible to all warps

    // ---- product 3: P = q*r + f0*I + f1*S + f2*Z ----
    epi_scaled(0.f, cf.f0, cf.f1, cf.f2);
    product(sb + VH, sb + VL);

    // ---- store result (fp32) ----
    #pragma unroll
    for (int n = 0; n < 8; n++) {
        int c0 = 8 * n + 2 * lr;
        *(float2*)(out + mb + (size_t)er0 * 64 + c0) =
            make_float2(acc[n][0], acc[n][1]);
        *(float2*)(out + mb + (size_t)er1 * 64 + c0) =
            make_float2(acc[n][2], acc[n][3]);
    }
}

extern "C" void kernel_launch(void* const* d_in, const int* in_sizes, int n_in,
                              void* d_out, int out_size)
{
    const float* X = (const float*)d_in[0];
    float* out = (float*)d_out;
    const int nmat = in_sizes[0] >> 12;

    Coeffs cf;
    {
        // Chebyshev coeffs of log on [1, 6.8] (closed form) -> monomial p0..p8
        const double a = 1.0, b = 6.8;
        const double m = 0.5 * (a + b);
        const double hh = 0.5 * (b - a);
        const double w = hh / m;
        const double rho = (1.0 - sqrt(1.0 - w * w)) / w;

        double c[DEG + 1];
        c[0] = log(m) - log1p(rho * rho);
        double rp = 1.0;
        for (int k = 1; k <= DEG; k++) {
            rp *= rho;
            c[k] = 2.0 * ((k & 1) ? rp : -rp) / (double)k;
        }
        double p[DEG + 1], Tm2[DEG + 1], Tm1[DEG + 1], Tc[DEG + 1];
        for (int i = 0; i <= DEG; i++) { p[i] = 0.0; Tm2[i] = 0.0; Tm1[i] = 0.0; }
        Tm2[0] = 1.0; p[0] += c[0];
        Tm1[1] = 1.0; p[1] += c[1];
        for (int k = 2; k <= DEG; k++) {
            for (int i = 0; i <= DEG; i++) Tc[i] = 0.0;
            for (int i = 0; i < k; i++) Tc[i + 1] += 2.0 * Tm1[i];
            for (int i = 0; i <= k - 2; i++) Tc[i] -= Tm2[i];
            for (int i = 0; i <= k; i++) p[i] += c[k] * Tc[i];
            for (int i = 0; i <= DEG; i++) { Tm2[i] = Tm1[i]; Tm1[i] = Tc[i]; }
        }

        // Sastre-style 3-product scheme coefficients (derived in round theory):
        const double c1 = p[7] / (2.0 * p[8]);
        const double c3 = p[6] - p[8] * c1 * c1;
        const double c5 = p[4] - c1 * p[5] + c1 * c1 * c3;
        const double c7 = (p[3] - c1 * c5) / c3;
        const double c4 = p[5] - p[8] * c7 - c3 * c1;
        const double c10 = p[2] - c4 * c7;
        const double c11 = p[1] - c5 * c7;
        const double c12 = p[0];

        // balance q and r for bf16 splitting
        double maxq = 0.0, maxr = 0.0;
        for (int i = 0; i <= 2000; i++) {
            double t = -1.0 + 2.0 * i / 2000.0;
            double W = t*t*t*t + c1 * t*t*t;
            double qv = p[8]*W + c3*t*t + c4*t + c5;
            double rv = W + c7*t;
            if (fabs(qv) > maxq) maxq = fabs(qv);
            if (fabs(rv) > maxr) maxr = fabs(rv);
        }
        const double gam = sqrt(maxq / maxr);

        cf.mshift = (float)m;
        cf.invh = (float)(1.0 / hh);
        cf.c1 = (float)c1;
        cf.qa = (float)(p[8] / gam);
        cf.qb = (float)(c3 / gam);
        cf.qc = (float)(c4 / gam);
        cf.qd = (float)(c5 / gam);
        cf.ra = (float)gam;
        cf.rb = (float)(gam * c7);
        cf.f0 = (float)c12;
        cf.f1 = (float)c11;
        cf.f2 = (float)c10;
    }

    cudaFuncSetAttribute(logmap_mma_kernel,
                         cudaFuncAttributeMaxDynamicSharedMemorySize, SMEM_TOTAL);
    logmap_mma_kernel<<<nmat, 128, SMEM_TOTAL>>>(X, out, cf);
}

// round 10
// speedup vs baseline: 1.0987x; 1.0987x over previous
#include <cuda_runtime.h>
#include <cuda_bf16.h>
#include <math.h>
#include <stdint.h>

// LogMap via matrix polynomial on the tensor pipe (portable mma.sync m16n8k16 bf16).
// log(X) = p(S), S=(X-m I)/h on [1,6.8]; p = deg-8 Chebyshev fit.
// Sastre 3-product scheme: Z=S^2; W=Z*V, V=Z+c1*S; p = q*r + lin.
// All S-dependences rewritten onto {V,Z} via S=(V-Z)/c1 so only TWO smem
// buffer pairs are needed (32KB): pair1 = S->V(in place), pair2 = Z->r.
// Fused post-P2 pass: q -> A-frags, lin -> acc, r -> smem, one Z/V read.
// 1 matrix/CTA, 4 warps; launch_bounds(128,5) -> 5 CTAs/SM (20 warps).

#define DEG 8
struct Coeffs {
    float mshift, invh, c1;
    float qa, qbz, qcv, qd;     // q = qa*W + qbz*Z + qcv*V + qd*I  (scaled 1/gam)
    float ra, rbv;              // r = ra*W + rbv*V - rbv*Z         (scaled gam)
    float f0, f1v, f2z;         // lin = f0*I + f1v*V + f2z*Z
};

// smem: pair1 = S/V (hi,lo), pair2 = Z/r (hi,lo); 4 x 8KB
#define SH 0
#define SL 8192
#define ZH 16384
#define ZL 24576
#define SMEM_TOTAL 32768

__device__ __forceinline__ uint32_t smem_u32(const void* p) {
    uint32_t a;
    asm("{ .reg .u64 t; cvta.to.shared.u64 t, %1; cvt.u32.u64 %0, t; }"
        : "=r"(a) : "l"(p));
    return a;
}

__device__ __forceinline__ uint32_t swoff(int r, int cb) {
    return (uint32_t)(r * 128 + ((((cb >> 4) ^ (r & 7))) << 4) + (cb & 15));
}

#define LDMX4(d, addr) \
    asm volatile("ldmatrix.sync.aligned.m8n8.x4.shared.b16 {%0,%1,%2,%3}, [%4];" \
        : "=r"((d)[0]), "=r"((d)[1]), "=r"((d)[2]), "=r"((d)[3]) : "r"(addr))

#define LDMX4T(d, addr) \
    asm volatile("ldmatrix.sync.aligned.m8n8.x4.trans.shared.b16 {%0,%1,%2,%3}, [%4];" \
        : "=r"((d)[0]), "=r"((d)[1]), "=r"((d)[2]), "=r"((d)[3]) : "r"(addr))

#define MMA(c, a, b0v, b1v) \
    asm volatile("mma.sync.aligned.m16n8k16.row.col.f32.bf16.bf16.f32 " \
        "{%0,%1,%2,%3}, {%4,%5,%6,%7}, {%8,%9}, {%0,%1,%2,%3};" \
        : "+f"((c)[0]), "+f"((c)[1]), "+f"((c)[2]), "+f"((c)[3]) \
        : "r"((a)[0]), "r"((a)[1]), "r"((a)[2]), "r"((a)[3]), "r"(b0v), "r"(b1v))

__device__ __forceinline__ uint32_t pk(float a, float b) {
    __nv_bfloat162 t = __floats2bfloat162_rn(a, b);
    return *reinterpret_cast<uint32_t*>(&t);
}
__device__ __forceinline__ float2 upk(uint32_t u) {
    __nv_bfloat162 t = *reinterpret_cast<__nv_bfloat162*>(&u);
    return __bfloat1622float2(t);
}
__device__ __forceinline__ float bhi(float v) {
    return __bfloat162float(__float2bfloat16_rn(v));
}

__device__ __forceinline__ void split_store8(const float* v, char* hi, char* lo) {
    float h0 = bhi(v[0]), h1 = bhi(v[1]), h2 = bhi(v[2]), h3 = bhi(v[3]);
    float h4 = bhi(v[4]), h5 = bhi(v[5]), h6 = bhi(v[6]), h7 = bhi(v[7]);
    *(uint4*)hi = make_uint4(pk(v[0], v[1]), pk(v[2], v[3]), pk(v[4], v[5]), pk(v[6], v[7]));
    *(uint4*)lo = make_uint4(pk(v[0]-h0, v[1]-h1), pk(v[2]-h2, v[3]-h3),
                             pk(v[4]-h4, v[5]-h5), pk(v[6]-h6, v[7]-h7));
}

__global__ void __launch_bounds__(128, 5)
logmap_mma_kernel(const float* __restrict__ X, float* __restrict__ out, Coeffs cf)
{
    extern __shared__ char sm[];
    const uint32_t sb = smem_u32(sm);
    const int tid = threadIdx.x;
    const int w = tid >> 5;              // warp owns rows [16w, 16w+16)
    const int l = tid & 31;
    const int sr = 16 * w;
    const int lq = l >> 2, lr = l & 3;
    const int lmr = l & 15;
    const int lmc16 = (l >> 4) & 1;
    const int key = lmr & 7;
    const size_t mb = (size_t)blockIdx.x * 4096;

    uint32_t colx[4];
    #pragma unroll
    for (int j = 0; j < 4; j++) colx[j] = (uint32_t)((((2*j + lmc16) ^ key)) << 4);
    const uint32_t arow = (uint32_t)((sr + lmr) * 128);
    const int er0 = sr + lq, er1 = er0 + 8;

    // ---- load X (half-row/thread), S = (X - m I)/h, write S hi/lo -> pair1 ----
    {
        const int row = sr + (l >> 1);
        const int c0 = 32 * (l & 1);
        const float4* xr = (const float4*)(X + mb + (size_t)row * 64 + c0);
        float v[32];
        #pragma unroll
        for (int q = 0; q < 8; q++) {
            float4 f = xr[q];
            v[4*q] = f.x; v[4*q+1] = f.y; v[4*q+2] = f.z; v[4*q+3] = f.w;
        }
        #pragma unroll
        for (int i = 0; i < 32; i++) {
            float t = v[i];
            if (c0 + i == row) t -= cf.mshift;
            v[i] = t * cf.invh;
        }
        #pragma unroll
        for (int q = 0; q < 4; q++) {
            uint32_t o = swoff(row, 2 * c0 + 16 * q);
            split_store8(v + 8 * q, sm + SH + o, sm + SL + o);
        }
    }
    __syncthreads();                       // (1) S visible

    float acc[8][4];
    uint32_t ah[4][4], al[4][4];

    auto zacc = [&] {
        #pragma unroll
        for (int n = 0; n < 8; n++)
            #pragma unroll
            for (int q = 0; q < 4; q++) acc[n][q] = 0.f;
    };

    auto ldaS = [&] {
        #pragma unroll
        for (int kk = 0; kk < 4; kk++) {
            uint32_t o = arow + colx[kk];
            LDMX4(ah[kk], sb + SH + o);
            LDMX4(al[kk], sb + SL + o);
        }
    };

    auto cvtA = [&] {
        #pragma unroll
        for (int kk = 0; kk < 4; kk++) {
            float c00 = acc[2*kk][0],   c01 = acc[2*kk][1];
            float c02 = acc[2*kk][2],   c03 = acc[2*kk][3];
            float d00 = acc[2*kk+1][0], d01 = acc[2*kk+1][1];
            float d02 = acc[2*kk+1][2], d03 = acc[2*kk+1][3];
            ah[kk][0] = pk(c00, c01); ah[kk][1] = pk(c02, c03);
            ah[kk][2] = pk(d00, d01); ah[kk][3] = pk(d02, d03);
            al[kk][0] = pk(c00 - bhi(c00), c01 - bhi(c01));
            al[kk][1] = pk(c02 - bhi(c02), c03 - bhi(c03));
            al[kk][2] = pk(d00 - bhi(d00), d01 - bhi(d01));
            al[kk][3] = pk(d02 - bhi(d02), d03 - bhi(d03));
        }
    };

    // acc += A(frags)*B(smem hi/lo); 8 live B regs
    auto product = [&](uint32_t bhBase, uint32_t blBase) {
        #pragma unroll
        for (int kk = 0; kk < 4; kk++) {
            const uint32_t kbo = (uint32_t)((16*kk + lmr) * 128);
            #pragma unroll
            for (int j = 0; j < 4; j++) {
                uint32_t o = kbo + colx[j];
                uint32_t b[4];
                LDMX4T(b, bhBase + o);
                MMA(acc[2*j],   ah[kk], b[0], b[1]);
                MMA(acc[2*j+1], ah[kk], b[2], b[3]);
                MMA(acc[2*j],   al[kk], b[0], b[1]);
                MMA(acc[2*j+1], al[kk], b[2], b[3]);
                LDMX4T(b, blBase + o);
                MMA(acc[2*j],   ah[kk], b[0], b[1]);
                MMA(acc[2*j+1], ah[kk], b[2], b[3]);
            }
        }
    };

    auto stacc = [&](int hB, int lB) {
        #pragma unroll
        for (int n = 0; n < 8; n++) {
            int cb = 16 * n + 4 * lr;
            uint32_t o0 = swoff(er0, cb), o1 = swoff(er1, cb);
            float a0 = acc[n][0], a1 = acc[n][1];
            float a2 = acc[n][2], a3 = acc[n][3];
            *(uint32_t*)(sm + hB + o0) = pk(a0, a1);
            *(uint32_t*)(sm + hB + o1) = pk(a2, a3);
            *(uint32_t*)(sm + lB + o0) = pk(a0 - bhi(a0), a1 - bhi(a1));
            *(uint32_t*)(sm + lB + o1) = pk(a2 - bhi(a2), a3 - bhi(a3));
        }
    };

    // ---- P1: Z = S*S ----
    ldaS();
    zacc();
    product(sb + SH, sb + SL);
    stacc(ZH, ZL);                         // Z -> pair2
    cvtA();                                // A <- Z
    __syncthreads();                       // (2) all P1 reads of S done

    // ---- V = Z + c1*S, in place over pair1 (own cells) ----
    #pragma unroll
    for (int n = 0; n < 8; n++) {
        int cb = 16 * n + 4 * lr;
        uint32_t o0 = swoff(er0, cb), o1 = swoff(er1, cb);
        float2 s0 = upk(*(uint32_t*)(sm + SH + o0));
        float2 s0l = upk(*(uint32_t*)(sm + SL + o0));
        float2 s1 = upk(*(uint32_t*)(sm + SH + o1));
        float2 s1l = upk(*(uint32_t*)(sm + SL + o1));
        float a0 = acc[n][0] + cf.c1 * (s0.x + s0l.x);
        float a1 = acc[n][1] + cf.c1 * (s0.y + s0l.y);
        float a2 = acc[n][2] + cf.c1 * (s1.x + s1l.x);
        float a3 = acc[n][3] + cf.c1 * (s1.y + s1l.y);
        *(uint32_t*)(sm + SH + o0) = pk(a0, a1);
        *(uint32_t*)(sm + SH + o1) = pk(a2, a3);
        *(uint32_t*)(sm + SL + o0) = pk(a0 - bhi(a0), a1 - bhi(a1));
        *(uint32_t*)(sm + SL + o1) = pk(a2 - bhi(a2), a3 - bhi(a3));
    }
    __syncthreads();                       // (3) V visible

    // ---- P2: W = Z*V ----
    zacc();
    product(sb + SH, sb + SL);

    // ---- fused pass: q -> frags, r -> pair2 (over Z), lin -> acc ----
    // reads Z(pair2),V(pair1) own rows only; r writes own rows only -> no sync
    #pragma unroll
    for (int g = 0; g < 4; g++) {
        uint32_t zh[4], zl[4], vh[4], vl[4];
        uint32_t o = arow + colx[g];
        LDMX4(zh, sb + ZH + o);
        LDMX4(zl, sb + ZL + o);
        LDMX4(vh, sb + SH + o);
        LDMX4(vl, sb + SL + o);
        #pragma unroll
        for (int q = 0; q < 4; q++) {
            float2 z1 = upk(zh[q]), z2 = upk(zl[q]);
            float2 v1 = upk(vh[q]), v2 = upk(vl[q]);
            float zx = z1.x + z2.x, zy = z1.y + z2.y;
            float vx = v1.x + v2.x, vy = v1.y + v2.y;
            int n = 2 * g + (q >> 1), c = (q & 1) * 2;
            int row = (q & 1) ? er1 : er0;
            int col0 = 8 * n + 2 * lr;
            float w0 = acc[n][c], w1 = acc[n][c + 1];
            // q (diag add, then to A-frags)
            float q0 = cf.qa * w0 + cf.qbz * zx + cf.qcv * vx;
            float q1 = cf.qa * w1 + cf.qbz * zy + cf.qcv * vy;
            if (col0 == row)     q0 += cf.qd;
            if (col0 + 1 == row) q1 += cf.qd;
            ah[g][q] = pk(q0, q1);
            al[g][q] = pk(q0 - bhi(q0), q1 - bhi(q1));
            // r -> pair2
            float r0 = cf.ra * w0 + cf.rbv * (vx - zx);
            float r1 = cf.ra * w1 + cf.rbv * (vy - zy);
            uint32_t so = swoff(row, 16 * n + 4 * lr);
            *(uint32_t*)(sm + ZH + so) = pk(r0, r1);
            *(uint32_t*)(sm + ZL + so) = pk(r0 - bhi(r0), r1 - bhi(r1));
            // lin -> acc (P3 init)
            float f0 = cf.f1v * vx + cf.f2z * zx;
            float f1 = cf.f1v * vy + cf.f2z * zy;
            if (col0 == row)     f0 += cf.f0;
            if (col0 + 1 == row) f1 += cf.f0;
            acc[n][c] = f0;
            acc[n][c + 1] = f1;
        }
    }
    __syncthreads();                       // (4) r visible

    // ---- P3: P = lin + q*r ----
    product(sb + ZH, sb + ZL);

    // ---- store result (fp32) ----
    #pragma unroll
    for (int n = 0; n < 8; n++) {
        int c0 = 8 * n + 2 * lr;
        *(float2*)(out + mb + (size_t)er0 * 64 + c0) =
            make_float2(acc[n][0], acc[n][1]);
        *(float2*)(out + mb + (size_t)er1 * 64 + c0) =
            make_float2(acc[n][2], acc[n][3]);
    }
}

extern "C" void kernel_launch(void* const* d_in, const int* in_sizes, int n_in,
                              void* d_out, int out_size)
{
    const float* X = (const float*)d_in[0];
    float* out = (float*)d_out;
    const int nmat = in_sizes[0] >> 12;

    Coeffs cf;
    {
        // Chebyshev coeffs of log on [1, 6.8] -> monomial p0..p8
        const double a = 1.0, b = 6.8;
        const double m = 0.5 * (a + b);
        const double hh = 0.5 * (b - a);
        const double w = hh / m;
        const double rho = (1.0 - sqrt(1.0 - w * w)) / w;

        double c[DEG + 1];
        c[0] = log(m) - log1p(rho * rho);
        double rp = 1.0;
        for (int k = 1; k <= DEG; k++) {
            rp *= rho;
            c[k] = 2.0 * ((k & 1) ? rp : -rp) / (double)k;
        }
        double p[DEG + 1], Tm2[DEG + 1], Tm1[DEG + 1], Tc[DEG + 1];
        for (int i = 0; i <= DEG; i++) { p[i] = 0.0; Tm2[i] = 0.0; Tm1[i] = 0.0; }
        Tm2[0] = 1.0; p[0] += c[0];
        Tm1[1] = 1.0; p[1] += c[1];
        for (int k = 2; k <= DEG; k++) {
            for (int i = 0; i <= DEG; i++) Tc[i] = 0.0;
            for (int i = 0; i < k; i++) Tc[i + 1] += 2.0 * Tm1[i];
            for (int i = 0; i <= k - 2; i++) Tc[i] -= Tm2[i];
            for (int i = 0; i <= k; i++) p[i] += c[k] * Tc[i];
            for (int i = 0; i <= DEG; i++) { Tm2[i] = Tm1[i]; Tm1[i] = Tc[i]; }
        }

        // Sastre 3-product scheme
        const double c1 = p[7] / (2.0 * p[8]);
        const double c3 = p[6] - p[8] * c1 * c1;
        const double c5 = p[4] - c1 * p[5] + c1 * c1 * c3;
        const double c7 = (p[3] - c1 * c5) / c3;
        const double c4 = p[5] - p[8] * c7 - c3 * c1;
        const double c10 = p[2] - c4 * c7;
        const double c11 = p[1] - c5 * c7;
        const double c12 = p[0];

        // balance q, r
        double maxq = 0.0, maxr = 0.0;
        for (int i = 0; i <= 2000; i++) {
            double t = -1.0 + 2.0 * i / 2000.0;
            double W = t*t*t*t + c1 * t*t*t;
            double qv = p[8]*W + c3*t*t + c4*t + c5;
            double rv = W + c7*t;
            if (fabs(qv) > maxq) maxq = fabs(qv);
            if (fabs(rv) > maxr) maxr = fabs(rv);
        }
        const double gam = sqrt(maxq / maxr);

        // S = (V - Z)/c1 rewrites
        const double qa = p[8] / gam, qb = c3 / gam, qc = c4 / gam, qd = c5 / gam;
        const double ra = gam, rb = gam * c7;

        cf.mshift = (float)m;
        cf.invh = (float)(1.0 / hh);
        cf.c1 = (float)c1;
        cf.qa = (float)qa;
        cf.qbz = (float)(qb - qc / c1);
        cf.qcv = (float)(qc / c1);
        cf.qd = (float)qd;
        cf.ra = (float)ra;
        cf.rbv = (float)(rb / c1);
        cf.f0 = (float)c12;
        cf.f1v = (float)(c11 / c1);
        cf.f2z = (float)(c10 - c11 / c1);
    }

    cudaFuncSetAttribute(logmap_mma_kernel,
                         cudaFuncAttributeMaxDynamicSharedMemorySize, SMEM_TOTAL);
    logmap_mma_kernel<<<nmat, 128, SMEM_TOTAL>>>(X, out, cf);
}